// round 6
// baseline (speedup 1.0000x reference)
#include <cuda_runtime.h>
#include <cuda_fp16.h>
#include <stdint.h>

#define M_DIM 2048
#define N_DIM 8192
#define K_DIM 8192

__device__ __align__(128) __half g_A[(size_t)M_DIM * K_DIM];   // 33.5 MB
__device__ __align__(128) __half g_B[(size_t)N_DIM * K_DIM];   // 134 MB

#define FULL_TILES 888
#define TAIL_TILES 136
__device__ __align__(128) float g_part[(size_t)TAIL_TILES * 128 * 128]; // 8.9 MB

// ---------------------------------------------------------------------------
// Kernel 1: x (fp32) -> fp16
// ---------------------------------------------------------------------------
__global__ void split_x_kernel(const float* __restrict__ x) {
    size_t i = ((size_t)blockIdx.x * blockDim.x + threadIdx.x) * 8;
    float4 v0 = *reinterpret_cast<const float4*>(x + i);
    float4 v1 = *reinterpret_cast<const float4*>(x + i + 4);
    __half2 h0 = __floats2half2_rn(v0.x, v0.y);
    __half2 h1 = __floats2half2_rn(v0.z, v0.w);
    __half2 h2 = __floats2half2_rn(v1.x, v1.y);
    __half2 h3 = __floats2half2_rn(v1.z, v1.w);
    uint4 out;
    out.x = *reinterpret_cast<uint32_t*>(&h0);
    out.y = *reinterpret_cast<uint32_t*>(&h1);
    out.z = *reinterpret_cast<uint32_t*>(&h2);
    out.w = *reinterpret_cast<uint32_t*>(&h3);
    *reinterpret_cast<uint4*>(&g_A[i]) = out;
}

// ---------------------------------------------------------------------------
// Kernel 2: dequant. 4 groups (32 weights) per thread.
// ---------------------------------------------------------------------------
__global__ void dequant_kernel(const int* __restrict__ p,
                               const float* __restrict__ cb) {
    int t = blockIdx.x * blockDim.x + threadIdx.x;      // 0 .. 2097151
    const int4* p4 = reinterpret_cast<const int4*>(p) + (size_t)t * 3;
    int4 pa = p4[0], pb = p4[1], pc = p4[2];
    int by[12] = {pa.x, pa.y, pa.z, pa.w, pb.x, pb.y, pb.z, pb.w,
                  pc.x, pc.y, pc.z, pc.w};

    const float4* c4 = reinterpret_cast<const float4*>(cb) + (size_t)(t >> 2) * 2;
    float4 f0 = __ldg(c4), f1 = __ldg(c4 + 1);
    uint64_t t0 = (uint64_t)__half_as_ushort(__float2half_rn(f0.x))
                | ((uint64_t)__half_as_ushort(__float2half_rn(f0.y)) << 16)
                | ((uint64_t)__half_as_ushort(__float2half_rn(f0.z)) << 32)
                | ((uint64_t)__half_as_ushort(__float2half_rn(f0.w)) << 48);
    uint64_t t1 = (uint64_t)__half_as_ushort(__float2half_rn(f1.x))
                | ((uint64_t)__half_as_ushort(__float2half_rn(f1.y)) << 16)
                | ((uint64_t)__half_as_ushort(__float2half_rn(f1.z)) << 32)
                | ((uint64_t)__half_as_ushort(__float2half_rn(f1.w)) << 48);

    uint4* dst = reinterpret_cast<uint4*>(g_B + (size_t)t * 32);
#pragma unroll
    for (int g = 0; g < 4; g++) {
        unsigned bits = (unsigned)by[3 * g] | ((unsigned)by[3 * g + 1] << 8)
                      | ((unsigned)by[3 * g + 2] << 16);
        uint32_t hv[8];
#pragma unroll
        for (int j = 0; j < 8; j++) {
            int idx = (bits >> (3 * j)) & 7;
            uint64_t tab = (idx & 4) ? t1 : t0;
            hv[j] = (uint32_t)(tab >> ((idx & 3) << 4)) & 0xFFFFu;
        }
        uint4 o;
        o.x = hv[0] | (hv[1] << 16);
        o.y = hv[2] | (hv[3] << 16);
        o.z = hv[4] | (hv[5] << 16);
        o.w = hv[6] | (hv[7] << 16);
        dst[g] = o;
    }
}

// ---------------------------------------------------------------------------
// Kernel 3: GEMM. fp16-acc mma (2x tensor rate), promote to fp32 every BK=64.
// BM=BN=128, BK=64, 4 warps (2x2), occ2, 3-stage cp.async, split-K tail.
// ---------------------------------------------------------------------------
#define BM 128
#define BN 128
#define BK 64
#define NSTAGE 3
#define A_BYTES (BM * BK * 2)
#define B_BYTES (BN * BK * 2)
#define STAGE_BYTES (A_BYTES + B_BYTES)
#define GEMM_SMEM (NSTAGE * STAGE_BYTES)
#define GTHREADS 128

__device__ __forceinline__ uint32_t smem_u32(const void* p) {
    uint32_t a;
    asm("{ .reg .u64 t; cvta.to.shared.u64 t, %1; cvt.u32.u64 %0, t; }"
        : "=r"(a) : "l"(p));
    return a;
}

__device__ __forceinline__ uint32_t swz(uint32_t base, int row, int chunk) {
    return base + row * 128 + (((chunk ^ row) & 7) << 4);
}

__device__ __forceinline__ void cp16(uint32_t dst, const void* src) {
    asm volatile("cp.async.cg.shared.global [%0], [%1], 16;\n"
                 :: "r"(dst), "l"(src));
}

__device__ __forceinline__ void ldsm4(uint32_t* r, uint32_t addr) {
    asm volatile("ldmatrix.sync.aligned.m8n8.x4.shared.b16 {%0,%1,%2,%3}, [%4];"
                 : "=r"(r[0]), "=r"(r[1]), "=r"(r[2]), "=r"(r[3]) : "r"(addr));
}

// fp16-accumulate mma: d/c are 2 packed f16x2 regs
__device__ __forceinline__ void mma16816h(uint32_t* c, const uint32_t* a,
                                          const uint32_t* b) {
    asm volatile(
        "mma.sync.aligned.m16n8k16.row.col.f16.f16.f16.f16 "
        "{%0,%1}, {%2,%3,%4,%5}, {%6,%7}, {%0,%1};\n"
        : "+r"(c[0]), "+r"(c[1])
        : "r"(a[0]), "r"(a[1]), "r"(a[2]), "r"(a[3]), "r"(b[0]), "r"(b[1]));
}

__device__ __forceinline__ void load_stage(uint32_t sb, int tid, int bm, int bn,
                                           int buf, int chunk) {
    const int k0 = chunk * BK;
    const uint32_t abase = sb + buf * STAGE_BYTES;
    const uint32_t bbase = abase + A_BYTES;
#pragma unroll
    for (int i = 0; i < 8; i++) {
        int c = tid + i * GTHREADS;
        int row = c >> 3, ch = c & 7;
        cp16(swz(abase, row, ch),
             g_A + (size_t)(bm + row) * K_DIM + k0 + ch * 8);
    }
#pragma unroll
    for (int i = 0; i < 8; i++) {
        int c = tid + i * GTHREADS;
        int row = c >> 3, ch = c & 7;
        cp16(swz(bbase, row, ch),
             g_B + (size_t)(bn + row) * K_DIM + k0 + ch * 8);
    }
    asm volatile("cp.async.commit_group;" ::: "memory");
}

__global__ void __launch_bounds__(GTHREADS, 2) gemm_kernel(float* __restrict__ y) {
    extern __shared__ char smem[];
    const uint32_t sb = smem_u32(smem);
    const int tid = threadIdx.x;
    const int w = tid >> 5, lane = tid & 31;
    const int wm = (w & 1) * 64;
    const int wn = (w >> 1) * 64;

    const int id = blockIdx.x;
    int tile, kz, iters;
    if (id < FULL_TILES) { tile = id; kz = 0; iters = 128; }
    else { int t = id - FULL_TILES; tile = FULL_TILES + (t >> 1); kz = t & 1; iters = 64; }
    const int kbase = kz * 64;
    const int bm = (tile & 15) * BM;
    const int bn = (tile >> 4) * BN;

    float acc[4][8][4];
#pragma unroll
    for (int i = 0; i < 4; i++)
#pragma unroll
        for (int j = 0; j < 8; j++)
#pragma unroll
            for (int r = 0; r < 4; r++) acc[i][j][r] = 0.0f;

#pragma unroll
    for (int s = 0; s < NSTAGE - 1; s++)
        load_stage(sb, tid, bm, bn, s, kbase + s);

    for (int it = 0; it < iters; it++) {
        if (it < iters - (NSTAGE - 1))
            asm volatile("cp.async.wait_group %0;" :: "n"(NSTAGE - 2) : "memory");
        else
            asm volatile("cp.async.wait_group 0;" ::: "memory");
        __syncthreads();

        const int j = it + NSTAGE - 1;
        if (j < iters) load_stage(sb, tid, bm, bn, j % NSTAGE, kbase + j);

        const int buf = it % NSTAGE;
        const uint32_t abase = sb + buf * STAGE_BYTES;
        const uint32_t bbase = abase + A_BYTES;

        // fp16 chunk accumulators, zeroed per iteration (BK=64 chunk)
        uint32_t acch[4][8][2];
#pragma unroll
        for (int mi = 0; mi < 4; mi++)
#pragma unroll
            for (int ni = 0; ni < 8; ni++) {
                acch[mi][ni][0] = 0u;
                acch[mi][ni][1] = 0u;
            }

#pragma unroll
        for (int kk = 0; kk < 4; kk++) {
            uint32_t ra[4][4], rb[4][4];
#pragma unroll
            for (int mi = 0; mi < 4; mi++) {
                int row = wm + mi * 16 + (lane & 15);
                int ch = kk * 2 + (lane >> 4);
                ldsm4(ra[mi], swz(abase, row, ch));
            }
#pragma unroll
            for (int np = 0; np < 4; np++) {
                int row = wn + np * 16 + (lane & 7) + ((lane >> 4) << 3);
                int ch = kk * 2 + ((lane >> 3) & 1);
                ldsm4(rb[np], swz(bbase, row, ch));
            }
#pragma unroll
            for (int mi = 0; mi < 4; mi++)
#pragma unroll
                for (int ni = 0; ni < 8; ni++)
                    mma16816h(acch[mi][ni], ra[mi],
                              &rb[ni >> 1][(ni & 1) * 2]);
        }

        // Promote fp16 chunk into fp32 accumulators
#pragma unroll
        for (int mi = 0; mi < 4; mi++)
#pragma unroll
            for (int ni = 0; ni < 8; ni++) {
                __half2 h0 = *reinterpret_cast<__half2*>(&acch[mi][ni][0]);
                __half2 h1 = *reinterpret_cast<__half2*>(&acch[mi][ni][1]);
                float2 f0 = __half22float2(h0);
                float2 f1 = __half22float2(h1);
                acc[mi][ni][0] += f0.x;
                acc[mi][ni][1] += f0.y;
                acc[mi][ni][2] += f1.x;
                acc[mi][ni][3] += f1.y;
            }
    }

    if (kz == 0) {
#pragma unroll
        for (int mi = 0; mi < 4; mi++) {
#pragma unroll
            for (int ni = 0; ni < 8; ni++) {
                int row = bm + wm + mi * 16 + (lane >> 2);
                int col = bn + wn + ni * 8 + (lane & 3) * 2;
                *reinterpret_cast<float2*>(&y[(size_t)row * N_DIM + col]) =
                    make_float2(acc[mi][ni][0], acc[mi][ni][1]);
                *reinterpret_cast<float2*>(&y[(size_t)(row + 8) * N_DIM + col]) =
                    make_float2(acc[mi][ni][2], acc[mi][ni][3]);
            }
        }
    } else {
        float* part = g_part + (size_t)(tile - FULL_TILES) * (BM * BN);
#pragma unroll
        for (int mi = 0; mi < 4; mi++) {
#pragma unroll
            for (int ni = 0; ni < 8; ni++) {
                int row = wm + mi * 16 + (lane >> 2);
                int col = wn + ni * 8 + (lane & 3) * 2;
                *reinterpret_cast<float2*>(&part[(size_t)row * BN + col]) =
                    make_float2(acc[mi][ni][0], acc[mi][ni][1]);
                *reinterpret_cast<float2*>(&part[(size_t)(row + 8) * BN + col]) =
                    make_float2(acc[mi][ni][2], acc[mi][ni][3]);
            }
        }
    }
}

// ---------------------------------------------------------------------------
// Kernel 4: combine partials for tail tiles.
// ---------------------------------------------------------------------------
__global__ void combine_kernel(float* __restrict__ y) {
    int idx = blockIdx.x * blockDim.x + threadIdx.x;    // 0 .. 557055
    int e = idx * 4;
    int s = e >> 14;
    int rem = e & 16383;
    int r = rem >> 7, c = rem & 127;
    int tile = FULL_TILES + s;
    int row = (tile & 15) * BM + r;
    int col = (tile >> 4) * BN + c;
    float4 p = *reinterpret_cast<const float4*>(&g_part[(size_t)e]);
    float4* yp = reinterpret_cast<float4*>(&y[(size_t)row * N_DIM + col]);
    float4 v = *yp;
    v.x += p.x; v.y += p.y; v.z += p.z; v.w += p.w;
    *yp = v;
}

// ---------------------------------------------------------------------------
extern "C" void kernel_launch(void* const* d_in, const int* in_sizes, int n_in,
                              void* d_out, int out_size) {
    const float* x  = (const float*)d_in[0];
    const int*   p  = (const int*)d_in[1];
    const float* cb = (const float*)d_in[2];
    float* y = (float*)d_out;

    split_x_kernel<<<(M_DIM * (size_t)K_DIM / 8) / 256, 256>>>(x);
    dequant_kernel<<<8192, 256>>>(p, cb);

    cudaFuncSetAttribute(gemm_kernel,
                         cudaFuncAttributeMaxDynamicSharedMemorySize, GEMM_SMEM);
    gemm_kernel<<<FULL_TILES + 2 * TAIL_TILES, GTHREADS, GEMM_SMEM>>>(y);

    combine_kernel<<<2176, 256>>>(y);
}

// round 7
// speedup vs baseline: 1.3209x; 1.3209x over previous
#include <cuda_runtime.h>
#include <cuda_fp16.h>
#include <stdint.h>

#define M_DIM 2048
#define N_DIM 8192
#define K_DIM 8192

__device__ __align__(128) __half g_A[(size_t)M_DIM * K_DIM];   // 33.5 MB
__device__ __align__(128) __half g_B[(size_t)N_DIM * K_DIM];   // 134 MB

// ---------------------------------------------------------------------------
// Kernel 1: x (fp32) -> fp16   (4 float4 per thread, MLP=4)
// ---------------------------------------------------------------------------
__global__ void split_x_kernel(const float* __restrict__ x) {
    size_t i = ((size_t)blockIdx.x * blockDim.x + threadIdx.x) * 16;
    float4 v0 = *reinterpret_cast<const float4*>(x + i);
    float4 v1 = *reinterpret_cast<const float4*>(x + i + 4);
    float4 v2 = *reinterpret_cast<const float4*>(x + i + 8);
    float4 v3 = *reinterpret_cast<const float4*>(x + i + 12);
    __half2 h0 = __floats2half2_rn(v0.x, v0.y);
    __half2 h1 = __floats2half2_rn(v0.z, v0.w);
    __half2 h2 = __floats2half2_rn(v1.x, v1.y);
    __half2 h3 = __floats2half2_rn(v1.z, v1.w);
    __half2 h4 = __floats2half2_rn(v2.x, v2.y);
    __half2 h5 = __floats2half2_rn(v2.z, v2.w);
    __half2 h6 = __floats2half2_rn(v3.x, v3.y);
    __half2 h7 = __floats2half2_rn(v3.z, v3.w);
    uint4 o0, o1;
    o0.x = *reinterpret_cast<uint32_t*>(&h0);
    o0.y = *reinterpret_cast<uint32_t*>(&h1);
    o0.z = *reinterpret_cast<uint32_t*>(&h2);
    o0.w = *reinterpret_cast<uint32_t*>(&h3);
    o1.x = *reinterpret_cast<uint32_t*>(&h4);
    o1.y = *reinterpret_cast<uint32_t*>(&h5);
    o1.z = *reinterpret_cast<uint32_t*>(&h6);
    o1.w = *reinterpret_cast<uint32_t*>(&h7);
    *reinterpret_cast<uint4*>(&g_A[i]) = o0;
    *reinterpret_cast<uint4*>(&g_A[i + 8]) = o1;
}

// ---------------------------------------------------------------------------
// Kernel 2: dequant. 4 groups (32 weights) per thread.
// ---------------------------------------------------------------------------
__global__ void dequant_kernel(const int* __restrict__ p,
                               const float* __restrict__ cb) {
    int t = blockIdx.x * blockDim.x + threadIdx.x;      // 0 .. 2097151
    const int4* p4 = reinterpret_cast<const int4*>(p) + (size_t)t * 3;
    int4 pa = p4[0], pb = p4[1], pc = p4[2];
    int by[12] = {pa.x, pa.y, pa.z, pa.w, pb.x, pb.y, pb.z, pb.w,
                  pc.x, pc.y, pc.z, pc.w};

    const float4* c4 = reinterpret_cast<const float4*>(cb) + (size_t)(t >> 2) * 2;
    float4 f0 = __ldg(c4), f1 = __ldg(c4 + 1);
    uint64_t t0 = (uint64_t)__half_as_ushort(__float2half_rn(f0.x))
                | ((uint64_t)__half_as_ushort(__float2half_rn(f0.y)) << 16)
                | ((uint64_t)__half_as_ushort(__float2half_rn(f0.z)) << 32)
                | ((uint64_t)__half_as_ushort(__float2half_rn(f0.w)) << 48);
    uint64_t t1 = (uint64_t)__half_as_ushort(__float2half_rn(f1.x))
                | ((uint64_t)__half_as_ushort(__float2half_rn(f1.y)) << 16)
                | ((uint64_t)__half_as_ushort(__float2half_rn(f1.z)) << 32)
                | ((uint64_t)__half_as_ushort(__float2half_rn(f1.w)) << 48);

    uint4* dst = reinterpret_cast<uint4*>(g_B + (size_t)t * 32);
#pragma unroll
    for (int g = 0; g < 4; g++) {
        unsigned bits = (unsigned)by[3 * g] | ((unsigned)by[3 * g + 1] << 8)
                      | ((unsigned)by[3 * g + 2] << 16);
        uint32_t hv[8];
#pragma unroll
        for (int j = 0; j < 8; j++) {
            int idx = (bits >> (3 * j)) & 7;
            uint64_t tab = (idx & 4) ? t1 : t0;
            hv[j] = (uint32_t)(tab >> ((idx & 3) << 4)) & 0xFFFFu;
        }
        uint4 o;
        o.x = hv[0] | (hv[1] << 16);
        o.y = hv[2] | (hv[3] << 16);
        o.z = hv[4] | (hv[5] << 16);
        o.w = hv[6] | (hv[7] << 16);
        dst[g] = o;
    }
}

// ---------------------------------------------------------------------------
// Kernel 3: GEMM. fp32-acc mma, BM=BN=128, BK=64, 4 warps, occ2, 3-stage.
// Per-iter order: wait/sync -> ldfrag(kk0) -> issue next cp.async -> mma loop.
// ---------------------------------------------------------------------------
#define BM 128
#define BN 128
#define BK 64
#define NSTAGE 3
#define NITER (K_DIM / BK)
#define A_BYTES (BM * BK * 2)
#define B_BYTES (BN * BK * 2)
#define STAGE_BYTES (A_BYTES + B_BYTES)
#define GEMM_SMEM (NSTAGE * STAGE_BYTES)
#define GTHREADS 128

__device__ __forceinline__ uint32_t smem_u32(const void* p) {
    uint32_t a;
    asm("{ .reg .u64 t; cvta.to.shared.u64 t, %1; cvt.u32.u64 %0, t; }"
        : "=r"(a) : "l"(p));
    return a;
}

__device__ __forceinline__ uint32_t swz(uint32_t base, int row, int chunk) {
    return base + row * 128 + (((chunk ^ row) & 7) << 4);
}

__device__ __forceinline__ void cp16(uint32_t dst, const void* src) {
    asm volatile("cp.async.cg.shared.global [%0], [%1], 16;\n"
                 :: "r"(dst), "l"(src));
}

__device__ __forceinline__ void ldsm4(uint32_t* r, uint32_t addr) {
    asm volatile("ldmatrix.sync.aligned.m8n8.x4.shared.b16 {%0,%1,%2,%3}, [%4];"
                 : "=r"(r[0]), "=r"(r[1]), "=r"(r[2]), "=r"(r[3]) : "r"(addr));
}

__device__ __forceinline__ void mma16816(float* c, const uint32_t* a,
                                         const uint32_t* b) {
    asm volatile(
        "mma.sync.aligned.m16n8k16.row.col.f32.f16.f16.f32 "
        "{%0,%1,%2,%3}, {%4,%5,%6,%7}, {%8,%9}, {%0,%1,%2,%3};\n"
        : "+f"(c[0]), "+f"(c[1]), "+f"(c[2]), "+f"(c[3])
        : "r"(a[0]), "r"(a[1]), "r"(a[2]), "r"(a[3]), "r"(b[0]), "r"(b[1]));
}

__device__ __forceinline__ void load_stage(uint32_t sb, int tid, int bm, int bn,
                                           int buf, int chunk) {
    const int k0 = chunk * BK;
    const uint32_t abase = sb + buf * STAGE_BYTES;
    const uint32_t bbase = abase + A_BYTES;
#pragma unroll
    for (int i = 0; i < 8; i++) {
        int c = tid + i * GTHREADS;
        int row = c >> 3, ch = c & 7;
        cp16(swz(abase, row, ch),
             g_A + (size_t)(bm + row) * K_DIM + k0 + ch * 8);
    }
#pragma unroll
    for (int i = 0; i < 8; i++) {
        int c = tid + i * GTHREADS;
        int row = c >> 3, ch = c & 7;
        cp16(swz(bbase, row, ch),
             g_B + (size_t)(bn + row) * K_DIM + k0 + ch * 8);
    }
    asm volatile("cp.async.commit_group;" ::: "memory");
}

__global__ void __launch_bounds__(GTHREADS, 2) gemm_kernel(float* __restrict__ y) {
    extern __shared__ char smem[];
    const uint32_t sb = smem_u32(smem);
    const int tid = threadIdx.x;
    const int w = tid >> 5, lane = tid & 31;
    const int wm = (w & 1) * 64;
    const int wn = (w >> 1) * 64;
    const int bm = (blockIdx.x & 15) * BM;     // M fastest -> B stripe shared
    const int bn = (blockIdx.x >> 4) * BN;

    float acc[4][8][4];
#pragma unroll
    for (int i = 0; i < 4; i++)
#pragma unroll
        for (int j = 0; j < 8; j++)
#pragma unroll
            for (int r = 0; r < 4; r++) acc[i][j][r] = 0.0f;

#pragma unroll
    for (int s = 0; s < NSTAGE - 1; s++)
        load_stage(sb, tid, bm, bn, s, s);

    uint32_t ra[2][4][4], rb[2][4][4];

    auto ldfrag = [&](uint32_t abase, uint32_t bbase, int kk, int pb) {
#pragma unroll
        for (int mi = 0; mi < 4; mi++) {
            int row = wm + mi * 16 + (lane & 15);
            int ch = kk * 2 + (lane >> 4);
            ldsm4(ra[pb][mi], swz(abase, row, ch));
        }
#pragma unroll
        for (int np = 0; np < 4; np++) {
            int row = wn + np * 16 + (lane & 7) + ((lane >> 4) << 3);
            int ch = kk * 2 + ((lane >> 3) & 1);
            ldsm4(rb[pb][np], swz(bbase, row, ch));
        }
    };

    for (int it = 0; it < NITER; it++) {
        if (it < NITER - (NSTAGE - 1))
            asm volatile("cp.async.wait_group %0;" :: "n"(NSTAGE - 2) : "memory");
        else
            asm volatile("cp.async.wait_group 0;" ::: "memory");
        __syncthreads();

        const int buf = it % NSTAGE;
        const uint32_t abase = sb + buf * STAGE_BYTES;
        const uint32_t bbase = abase + A_BYTES;

        // Fragments for kk=0 FIRST, so the HMMA stream starts ASAP; the
        // next-stage cp.async issue then overlaps with mma execution.
        ldfrag(abase, bbase, 0, 0);

        const int j = it + NSTAGE - 1;
        if (j < NITER) load_stage(sb, tid, bm, bn, j % NSTAGE, j);

#pragma unroll
        for (int kk = 0; kk < 4; kk++) {
            if (kk < 3) ldfrag(abase, bbase, kk + 1, (kk + 1) & 1);
            const int pb = kk & 1;
#pragma unroll
            for (int mi = 0; mi < 4; mi++)
#pragma unroll
                for (int ni = 0; ni < 8; ni++)
                    mma16816(acc[mi][ni], ra[pb][mi],
                             &rb[pb][ni >> 1][(ni & 1) * 2]);
        }
    }

#pragma unroll
    for (int mi = 0; mi < 4; mi++) {
#pragma unroll
        for (int ni = 0; ni < 8; ni++) {
            int row = bm + wm + mi * 16 + (lane >> 2);
            int col = bn + wn + ni * 8 + (lane & 3) * 2;
            *reinterpret_cast<float2*>(&y[(size_t)row * N_DIM + col]) =
                make_float2(acc[mi][ni][0], acc[mi][ni][1]);
            *reinterpret_cast<float2*>(&y[(size_t)(row + 8) * N_DIM + col]) =
                make_float2(acc[mi][ni][2], acc[mi][ni][3]);
        }
    }
}

// ---------------------------------------------------------------------------
extern "C" void kernel_launch(void* const* d_in, const int* in_sizes, int n_in,
                              void* d_out, int out_size) {
    const float* x  = (const float*)d_in[0];
    const int*   p  = (const int*)d_in[1];
    const float* cb = (const float*)d_in[2];
    float* y = (float*)d_out;

    split_x_kernel<<<(M_DIM * (size_t)K_DIM / 16) / 256, 256>>>(x);
    dequant_kernel<<<8192, 256>>>(p, cb);

    cudaFuncSetAttribute(gemm_kernel,
                         cudaFuncAttributeMaxDynamicSharedMemorySize, GEMM_SMEM);
    gemm_kernel<<<1024, GTHREADS, GEMM_SMEM>>>(y);
}